// round 14
// baseline (speedup 1.0000x reference)
#include <cuda_runtime.h>

#define NPHI 128
#define DEG  127

typedef unsigned long long u64;

// Coefficients C_j of a(w) = w^{-127} * sum_j C_j * (w^2)^j  (complex, 128 entries)
__device__ float2 g_coefA[NPHI];

// ---------------------------------------------------------------------------
// One recurrence step applied at a single position.
// v = (Ar, Ai, Br, Bi); vm1 = same at position-1; e = 0.5*e^{i phi_k}.
// ---------------------------------------------------------------------------
__device__ __forceinline__ float4 cstep(float4 vm1, float4 v0, float2 e) {
    float tAr = vm1.x + v0.x + vm1.z - v0.z;
    float tAi = vm1.y + v0.y + vm1.w - v0.w;
    float tBr = vm1.x - v0.x + vm1.z + v0.z;
    float tBi = vm1.y - v0.y + vm1.w + v0.w;
    float4 o;
    o.x = e.x * tAr - e.y * tAi;
    o.y = e.x * tAi + e.y * tAr;
    o.z = e.x * tBr + e.y * tBi;
    o.w = e.x * tBi - e.y * tBr;
    return o;
}

// ---------------------------------------------------------------------------
// Kernel 1: build the 128 complex coefficients from the phis (one block).
// EIGHT recurrence steps per __syncthreads: thread j reads positions j-8..j
// (float4 state, one LDS.128 each) and advances an 8-step wavefront locally,
// writing only position j. 127 = 7 + 15*8 steps -> 18 barriers total.
// Ends with threadfence + griddepcontrol.launch_dependents (PDL).
// ---------------------------------------------------------------------------
__global__ void qsp_coeff_kernel(const float* __restrict__ phis) {
    __shared__ float2 e2[NPHI];          // 0.5 * e^{i phi_k}
    __shared__ float4 V[2][NPHI + 8];    // position j lives at index j+8
    int j = threadIdx.x;  // 0..127

    float s, c;
    sincosf(phis[j], &s, &c);
    e2[j] = make_float2(0.5f * c, 0.5f * s);

    V[0][j + 8] = make_float4(0.f, 0.f, 0.f, 0.f);
    V[1][j + 8] = make_float4(0.f, 0.f, 0.f, 0.f);
    if (j < 8) {
        V[0][j] = make_float4(0.f, 0.f, 0.f, 0.f);
        V[1][j] = make_float4(0.f, 0.f, 0.f, 0.f);
    }
    __syncthreads();
    if (j == 0) V[0][8] = make_float4(c, s, 0.f, 0.f);  // A_0 = e^{i phi_0}
    __syncthreads();

    int p = 0;
    // steps k = 1..7 fused (7 steps)
    {
        float4 w[9];
#pragma unroll
        for (int i = 1; i <= 8; i++) w[i] = V[p][j + i];
#pragma unroll
        for (int t = 1; t <= 7; t++) {
            float2 e = e2[t];
#pragma unroll
            for (int i = 8; i > t; i--) w[i] = cstep(w[i - 1], w[i], e);
        }
        V[1][j + 8] = w[8];
        p = 1;
        __syncthreads();
    }
    // steps k = 8..127: 15 supersteps of 8
    for (int k = 8; k <= 120; k += 8) {
        int q = p ^ 1;
        float4 w[9];
#pragma unroll
        for (int i = 0; i <= 8; i++) w[i] = V[p][j + i];
#pragma unroll
        for (int t = 0; t < 8; t++) {
            float2 e = e2[k + t];
#pragma unroll
            for (int i = 8; i > t; i--) w[i] = cstep(w[i - 1], w[i], e);
        }
        V[q][j + 8] = w[8];
        p = q;
        __syncthreads();
    }

    float4 r = V[p][j + 8];
    g_coefA[j] = make_float2(r.x, r.y);
    __threadfence();
    asm volatile("griddepcontrol.launch_dependents;");
}

// ---------------------------------------------------------------------------
// Packed f32x2 helpers
// ---------------------------------------------------------------------------
__device__ __forceinline__ u64 pk2(float lo, float hi) {
    u64 r; asm("mov.b64 %0,{%1,%2};" : "=l"(r) : "f"(lo), "f"(hi)); return r;
}
__device__ __forceinline__ void upk2(u64 v, float& lo, float& hi) {
    asm("mov.b64 {%0,%1},%2;" : "=f"(lo), "=f"(hi) : "l"(v));
}
__device__ __forceinline__ u64 ffma2(u64 a, u64 b, u64 c) {
    u64 d; asm("fma.rn.f32x2 %0,%1,%2,%3;" : "=l"(d) : "l"(a), "l"(b), "l"(c)); return d;
}
__device__ __forceinline__ u64 fmul2(u64 a, u64 b) {
    u64 d; asm("mul.rn.f32x2 %0,%1,%2;" : "=l"(d) : "l"(a), "l"(b)); return d;
}
__device__ __forceinline__ u64 fsub2(u64 a, u64 b) {
    u64 d; asm("sub.rn.f32x2 %0,%1,%2;" : "=l"(d) : "l"(a), "l"(b)); return d;
}
__device__ __forceinline__ u64 neg2(u64 a) {
    return a ^ 0x8000000080000000ULL;  // flip both fp32 sign bits
}
// One LDS.128 -> two u64 (coefficient pair)
__device__ __forceinline__ void lds_v2b64(u64& a, u64& b, unsigned saddr) {
    asm volatile("ld.shared.v2.b64 {%0,%1},[%2];" : "=l"(a), "=l"(b) : "r"(saddr));
}

// ---------------------------------------------------------------------------
// Kernel 2: 4 thetas/thread = two packed (f32x2) Goertzel chains sharing one
// broadcast LDS.128 per coefficient. Block = 128 threads (fine-grained tail).
//   P(z) = sum_j C_j z^j,  z = e^{2i theta}:
//     b_k = C_k + 2*Re(z)*b_{k+1} - b_{k+2}
//     P   = b_0 - conj(z)*b_1
//   result = P * e^{-127 i theta}
// Prologue (theta loads + MUFU sincos) runs BEFORE griddepcontrol.wait.
// ---------------------------------------------------------------------------
__global__ void __launch_bounds__(128) qsp_main_kernel(const float* __restrict__ th,
                                                       float* __restrict__ out, int B) {
    int t = threadIdx.x;
    int base = (blockIdx.x * blockDim.x + t) * 4;
    bool valid = (base < B);
    int lbase = valid ? base : 0;

    float4 T = *(const float4*)(th + lbase);

    float zr0, zi0, zr1, zi1, zr2, zi2, zr3, zi3;   // z = e^{2i theta}
    float cm0, sm0, cm1, sm1, cm2, sm2, cm3, sm3;   // e^{i*127 theta}
    __sincosf(2.f * T.x, &zi0, &zr0);
    __sincosf(2.f * T.y, &zi1, &zr1);
    __sincosf(2.f * T.z, &zi2, &zr2);
    __sincosf(2.f * T.w, &zi3, &zr3);
    __sincosf(127.f * T.x, &sm0, &cm0);
    __sincosf(127.f * T.y, &sm1, &cm1);
    __sincosf(127.f * T.z, &sm2, &cm2);
    __sincosf(127.f * T.w, &sm3, &cm3);

    u64 ZRa = pk2(zr0, zr1), ZIa = pk2(zi0, zi1);
    u64 ZRb = pk2(zr2, zr3), ZIb = pk2(zi2, zi3);
    u64 Ya  = pk2(2.f * zr0, 2.f * zr1);           // 2*Re(z)
    u64 Yb  = pk2(2.f * zr2, 2.f * zr3);
    u64 CMa = pk2(cm0, cm1), SMa = pk2(sm0, sm1);
    u64 CMb = pk2(cm2, cm3), SMb = pk2(sm2, sm3);

    // Wait for the PDL predecessor's coefficients, then stage into smem.
    asm volatile("griddepcontrol.wait;" ::: "memory");

    __shared__ __align__(16) u64 sC[2 * NPHI];  // interleaved (CR, CI), lanes duplicated
    {
        float2 cc = g_coefA[t];                  // blockDim == NPHI: one pair each
        sC[2 * t]     = pk2(cc.x, cc.x);
        sC[2 * t + 1] = pk2(cc.y, cc.y);
    }
    __syncthreads();

    unsigned sbase = (unsigned)__cvta_generic_to_shared(sC);

    // Goertzel init: b_127 = C_127, b_128 = 0
    u64 B1ra, B1ia;
    lds_v2b64(B1ra, B1ia, sbase + 16u * DEG);
    u64 B1rb = B1ra, B1ib = B1ia;
    u64 B2ra = 0, B2ia = 0, B2rb = 0, B2ib = 0;

#pragma unroll 16
    for (int k = DEG - 1; k >= 0; k--) {
        u64 CR, CI;
        lds_v2b64(CR, CI, sbase + 16u * (unsigned)k);
        // chain a
        u64 tra = fsub2(CR, B2ra);
        u64 tia = fsub2(CI, B2ia);
        u64 nra = ffma2(Ya, B1ra, tra);
        u64 nia = ffma2(Ya, B1ia, tia);
        B2ra = B1ra; B2ia = B1ia; B1ra = nra; B1ia = nia;
        // chain b
        u64 trb = fsub2(CR, B2rb);
        u64 tib = fsub2(CI, B2ib);
        u64 nrb = ffma2(Yb, B1rb, trb);
        u64 nib = ffma2(Yb, B1ib, tib);
        B2rb = B1rb; B2ib = B1ib; B1rb = nrb; B1ib = nib;
    }
    // B1 = b_0, B2 = b_1.  P = b_0 - conj(z)*b_1
    u64 qra = ffma2(ZRa, B2ra, fmul2(ZIa, B2ia));
    u64 qia = ffma2(ZRa, B2ia, neg2(fmul2(ZIa, B2ra)));
    u64 Pra = fsub2(B1ra, qra);
    u64 Pia = fsub2(B1ia, qia);
    u64 qrb = ffma2(ZRb, B2rb, fmul2(ZIb, B2ib));
    u64 qib = ffma2(ZRb, B2ib, neg2(fmul2(ZIb, B2rb)));
    u64 Prb = fsub2(B1rb, qrb);
    u64 Pib = fsub2(B1ib, qib);

    // result = P * (cm, -sm)
    u64 FRa = ffma2(Pra, CMa, fmul2(Pia, SMa));
    u64 FIa = ffma2(Pia, CMa, neg2(fmul2(Pra, SMa)));
    u64 FRb = ffma2(Prb, CMb, fmul2(Pib, SMb));
    u64 FIb = ffma2(Pib, CMb, neg2(fmul2(Prb, SMb)));

    if (!valid) return;

    float r0, r1, r2, r3, i0, i1, i2, i3;
    upk2(FRa, r0, r1); upk2(FRb, r2, r3);
    upk2(FIa, i0, i1); upk2(FIb, i2, i3);

    *(float4*)(out + base)     = make_float4(r0, r1, r2, r3);  // real block
    *(float4*)(out + B + base) = make_float4(i0, i1, i2, i3);  // imag block
}

extern "C" void kernel_launch(void* const* d_in, const int* in_sizes, int n_in,
                              void* d_out, int out_size) {
    const float* th   = (const float*)d_in[0];
    const float* phis = (const float*)d_in[1];
    float* out = (float*)d_out;
    int B = in_sizes[0];

    qsp_coeff_kernel<<<1, NPHI>>>(phis);

    int nthreads = (B + 3) / 4;                 // 4 thetas per thread
    int blocks = (nthreads + 127) / 128;

    // PDL launch: main may begin (and run its sincos prologue) while the coeff
    // kernel is still finishing; griddepcontrol.wait gates the coefficient read.
    cudaLaunchConfig_t cfg = {};
    cfg.gridDim  = dim3((unsigned)blocks, 1, 1);
    cfg.blockDim = dim3(128, 1, 1);
    cudaLaunchAttribute attr[1];
    attr[0].id = cudaLaunchAttributeProgrammaticStreamSerialization;
    attr[0].val.programmaticStreamSerializationAllowed = 1;
    cfg.attrs = attr;
    cfg.numAttrs = 1;
    cudaLaunchKernelEx(&cfg, qsp_main_kernel, th, out, B);
}